// round 3
// baseline (speedup 1.0000x reference)
#include <cuda_runtime.h>
#include <stdint.h>

// Dims (fixed):
//   x:               [64, 64, 4096]   float32
//   cache:           [128, 512, 4096] float32
//   running_seqs:    [64] int32 (arange)
//   idx_salient_row: [64, 64] int32
//   out:             [64, 512, 4096]  float32
//
// out[i, r, :] = x[i, j_last, :] where j_last = last j with idx[i,j]==r
//                (== max matching j), else cache[running_seqs[i], r, :].

#define N_RUNNING    64
#define K_SALIENT    64
#define ROWS_PER_SEQ 512
#define HIDDEN       4096
#define VEC_PER_ROW  (HIDDEN / 4)     // 1024 float4 per row
#define THREADS      256
#define ROWS_PER_BLK 4                // all 4 rows share the same sequence i

__global__ __launch_bounds__(THREADS)
void mlpcache_gather_kernel(const float4* __restrict__ x,
                            const float4* __restrict__ cache,
                            const int*    __restrict__ running_seqs,
                            const int*    __restrict__ idx_salient,
                            float4*       __restrict__ out)
{
    const int row0 = blockIdx.x * ROWS_PER_BLK;      // 0 .. 32767, step 4
    const int i    = row0 >> 9;                      // sequence index
    const int r0   = row0 & (ROWS_PER_SEQ - 1);      // base row within seq

    // ── Barrier-free winner resolve ─────────────────────────────────────
    // Each lane loads 2 of the 64 idx entries for sequence i (shared by all
    // 4 rows of this block). Each warp redundantly computes the last-wins
    // winner (max matching j) for all 4 rows via REDUX — no shared memory,
    // no __syncthreads, no atomics. Loads are L1-broadcast (idx is 16 KB).
    const int lane = threadIdx.x & 31;
    const int j0   = lane;
    const int j1   = lane + 32;
    const int v0   = idx_salient[i * K_SALIENT + j0];
    const int v1   = idx_salient[i * K_SALIENT + j1];
    const int seq  = running_seqs[i];

    const float4* src[ROWS_PER_BLK];
    #pragma unroll
    for (int rr = 0; rr < ROWS_PER_BLK; ++rr) {
        const int r = r0 + rr;
        int m = -1;
        if (v0 == r) m = j0;
        if (v1 == r) m = j1;                 // j1 > j0, so plain overwrite ok
        const int w = __reduce_max_sync(0xFFFFFFFFu, m);
        src[rr] = (w >= 0)
            ? x     + ((size_t)(i * K_SALIENT + w))      * VEC_PER_ROW
            : cache + ((size_t)seq * ROWS_PER_SEQ + r)   * VEC_PER_ROW;
    }
    float4* __restrict__ dst = out + (size_t)row0 * VEC_PER_ROW;

    // ── Copy: 4 rows × 1024 float4, 256 threads ─────────────────────────
    // Per row: 4 front-batched streaming loads (MLP=4), then 4 streaming
    // stores. Row index is compile-time per unrolled chunk.
    #pragma unroll
    for (int rr = 0; rr < ROWS_PER_BLK; ++rr) {
        const float4* __restrict__ s = src[rr];
        float4*       __restrict__ d = dst + rr * VEC_PER_ROW;
        float4 v[4];
        #pragma unroll
        for (int k = 0; k < 4; ++k)
            v[k] = __ldcs(s + threadIdx.x + k * THREADS);
        #pragma unroll
        for (int k = 0; k < 4; ++k)
            __stcs(d + threadIdx.x + k * THREADS, v[k]);
    }
}

extern "C" void kernel_launch(void* const* d_in, const int* in_sizes, int n_in,
                              void* d_out, int out_size)
{
    const float4* x     = (const float4*)d_in[0];
    const float4* cache = (const float4*)d_in[1];
    const int* running  = (const int*)d_in[2];
    const int* idx      = (const int*)d_in[3];
    float4* out         = (float4*)d_out;

    mlpcache_gather_kernel<<<(N_RUNNING * ROWS_PER_SEQ) / ROWS_PER_BLK, THREADS>>>(
        x, cache, running, idx, out);
}

// round 4
// speedup vs baseline: 1.0255x; 1.0255x over previous
#include <cuda_runtime.h>
#include <stdint.h>

// Dims (fixed):
//   x:               [64, 64, 4096]   float32
//   cache:           [128, 512, 4096] float32
//   running_seqs:    [64] int32 (arange)
//   idx_salient_row: [64, 64] int32
//   out:             [64, 512, 4096]  float32
//
// out[i, r, :] = x[i, j_last, :] where j_last = last j with idx[i,j]==r
//                (== max matching j), else cache[running_seqs[i], r, :].

#define N_RUNNING    64
#define K_SALIENT    64
#define ROWS_PER_SEQ 512
#define HIDDEN       4096
#define THREADS      256
// Per row: 4096 floats = 512 float8 (32B) vectors; 256 threads -> 2 each.
#define V8_PER_ROW   (HIDDEN / 8)     // 512

// 256-bit global load/store (sm_100a: LDG.E.256 / STG.E.256), streaming hint.
__device__ __forceinline__ void ldg256_cs(const float* p, float* v) {
    asm volatile("ld.global.cs.v8.f32 {%0,%1,%2,%3,%4,%5,%6,%7}, [%8];"
                 : "=f"(v[0]), "=f"(v[1]), "=f"(v[2]), "=f"(v[3]),
                   "=f"(v[4]), "=f"(v[5]), "=f"(v[6]), "=f"(v[7])
                 : "l"(p));
}
__device__ __forceinline__ void stg256_cs(float* p, const float* v) {
    asm volatile("st.global.cs.v8.f32 [%0], {%1,%2,%3,%4,%5,%6,%7,%8};"
                 :: "l"(p),
                    "f"(v[0]), "f"(v[1]), "f"(v[2]), "f"(v[3]),
                    "f"(v[4]), "f"(v[5]), "f"(v[6]), "f"(v[7])
                 : "memory");
}

__global__ __launch_bounds__(THREADS, 8)
void mlpcache_gather_kernel(const float* __restrict__ x,
                            const float* __restrict__ cache,
                            const int*   __restrict__ running_seqs,
                            const int*   __restrict__ idx_salient,
                            float*       __restrict__ out)
{
    const int row = blockIdx.x;            // 0 .. 64*512-1 (one row per block)
    const int i   = row >> 9;              // sequence index
    const int r   = row & (ROWS_PER_SEQ - 1);

    // Barrier-free last-wins resolve: each lane checks 2 of the 64 idx
    // entries; REDUX gives winner = max matching j. Loads are L1-broadcast.
    const int lane = threadIdx.x & 31;
    const int v0 = idx_salient[i * K_SALIENT + lane];
    const int v1 = idx_salient[i * K_SALIENT + lane + 32];
    int m = -1;
    if (v0 == r) m = lane;
    if (v1 == r) m = lane + 32;            // lane+32 > lane: overwrite = last-wins
    const int w = __reduce_max_sync(0xFFFFFFFFu, m);

    const float* __restrict__ src = (w >= 0)
        ? x     + ((size_t)(i * K_SALIENT + w)) * HIDDEN
        : cache + ((size_t)running_seqs[i] * ROWS_PER_SEQ + r) * HIDDEN;
    float* __restrict__ dst = out + (size_t)row * HIDDEN;

    // 2 × 256-bit streaming loads front-batched, then 2 × 256-bit stores.
    const int c0 = threadIdx.x * 8;
    const int c1 = c0 + THREADS * 8;
    float a[8], b[8];
    ldg256_cs(src + c0, a);
    ldg256_cs(src + c1, b);
    stg256_cs(dst + c0, a);
    stg256_cs(dst + c1, b);
}

extern "C" void kernel_launch(void* const* d_in, const int* in_sizes, int n_in,
                              void* d_out, int out_size)
{
    const float* x     = (const float*)d_in[0];
    const float* cache = (const float*)d_in[1];
    const int* running = (const int*)d_in[2];
    const int* idx     = (const int*)d_in[3];
    float* out         = (float*)d_out;

    mlpcache_gather_kernel<<<N_RUNNING * ROWS_PER_SEQ, THREADS>>>(
        x, cache, running, idx, out);
}